// round 12
// baseline (speedup 1.0000x reference)
#include <cuda_runtime.h>

#define B_VOX   256
#define NPC     40
#define NE      32
#define ORD     8                    // EPG orders per lane
#define LPC     4                    // lanes per compartment (32 orders)
#define CPW     8                    // compartments per warp
#define VPB     4                    // voxels per block
#define WARPS_V (NPC / CPW)          // 5 warps per voxel
#define WARPS   (WARPS_V * VPB)      // 20 warps per block
#define THREADS (WARPS * 32)         // 640

// y-form EPG: y_{k+1} = S^2 · M · y_k  (y = S·x, E = S·M·S, M = D·T·D blockdiag)
// sub-lane s = lane&3 holds orders 8s+1..8s+8 as F[8],G[8],u[8] (u = C·Z);
// compartment = (wz%5)*8 + (lane>>2); voxel = blockIdx.x*VPB + wz/5.
// Weight w folded into initial state (linearity) -> echo_k = mG[0] directly.
// M per order:  mF = A·F + B·G + u ;  mG = B·F + A·G - u
//               u' = CD·(G - F) + Ez·u  (CD = C·Dz) ;  mx0 = e2²·x0
// S² shift: F[0]<-prev mF[6] (s0: mG[0]); F[1]<-prev mF[7] (s0: mx0);
//           F[j]=mF[j-2]; G[j]=mG[j+2]; G[6]<-next mG[0] (s3: 0); G[7]<-next mG[1] (s3: 0)
//           x0<-mG[1] (s0); echo_k = s0 mG[0]

__global__ __launch_bounds__(THREADS) void epg_kernel(
    const float* __restrict__ refoc,    // (256,)
    const float* __restrict__ t2s,      // (256, 40)
    const float* __restrict__ wts,      // (256, 40)
    float* __restrict__ out)            // (256, 32)
{
    const int lane = threadIdx.x & 31;
    const int wz   = threadIdx.x >> 5;
    const int vv   = wz / WARPS_V;           // voxel slot within block
    const int wv   = wz % WARPS_V;           // warp within voxel
    const int b    = blockIdx.x * VPB + vv;
    const int s    = lane & (LPC - 1);
    const int grp  = lane >> 2;
    const bool sLo = (s == 0);
    const bool sHi = (s == LPC - 1);
    const unsigned FULL = 0xFFFFFFFFu;

    __shared__ float smem[VPB][NPC][NE + 1]; // echo rows (+1 pad, conflict-free STS)
    __shared__ float part[VPB][WARPS_V][NE]; // per-warp partials

    // issue all global loads first (overlap latency with MUFU prologue)
    const int   c    = wv * CPW + grp;
    const float t2   = __ldg(&t2s[b * NPC + c]);
    const float w    = __ldg(&wts[b * NPC + c]);
    const float ang  = __ldg(&refoc[b]);

    // per-voxel rotation constants — fast MUFU path
    const float a  = ang * 0.017453292519943295f;
    const float sa = __sinf(a);
    const float ca = __cosf(a);
    const float c2 = 0.5f * (1.0f + ca);     // cos^2(a/2)
    const float s2 = 0.5f * (1.0f - ca);     // sin^2(a/2)
    const float ch = sqrtf(c2);              // a/2 in (60°,90°] -> both roots >= 0
    const float sh = sqrtf(s2);
    const float e1   = 0.99501247919268231f; // exp(-5/1000)
    const float e1sq = e1 * e1;

    // per-compartment fused coefficients — fast exp/rcp
    const float e2   = __expf(-5.0f * __frcp_rn(t2));
    const float e2sq = e2 * e2;
    const float A    = c2 * e2sq;
    const float Bc   = s2 * e2sq;
    const float Cc   = sa * e2 * e1;
    const float Dz   = 0.5f * sa * e1 * e2;
    const float Ez   = ca * e1sq;
    const float CD   = Cc * Dz;              // u-recurrence coefficient

    // init y0 = S·x0, pre-scaled by the compartment weight (linearity)
    float F[ORD], G[ORD], u[ORD];
    #pragma unroll
    for (int j = 0; j < ORD; ++j) { F[j] = 0.f; G[j] = 0.f; u[j] = 0.f; }
    if (sLo) F[0] = w * sh;
    float x0 = w * ch;                       // meaningful on sub-lane 0

    #pragma unroll                            // FULL unroll: no rotation MOVs, no branch
    for (int k = 0; k < NE; ++k) {
        // ---- M = D·T·D (all local, u = C·Z form) ----
        float mF[ORD], mG[ORD];
        #pragma unroll
        for (int j = 0; j < ORD; ++j) {
            mF[j] = fmaf(A,  F[j], fmaf(Bc, G[j],  u[j]));
            mG[j] = fmaf(Bc, F[j], fmaf(A,  G[j], -u[j]));
            u[j]  = fmaf(CD, G[j], fmaf(-CD, F[j], Ez * u[j]));
        }
        const float mx0 = e2sq * x0;

        // ---- S²: one shuffle segment, 4 shfls serve all 8 compartments ----
        const float cF0 = __shfl_up_sync  (FULL, mF[ORD-2], 1, LPC);
        const float cF1 = __shfl_up_sync  (FULL, mF[ORD-1], 1, LPC);
        const float cG0 = __shfl_down_sync(FULL, mG[0],     1, LPC);
        const float cG1 = __shfl_down_sync(FULL, mG[1],     1, LPC);

        if (sLo) smem[vv][c][k] = mG[0];     // pre-weighted echo_k, bare STS

        F[0] = sLo ? mG[0] : cF0;
        F[1] = sLo ? mx0   : cF1;
        #pragma unroll
        for (int j = 2; j < ORD; ++j) F[j] = mF[j - 2];
        #pragma unroll
        for (int j = 0; j < ORD - 2; ++j) G[j] = mG[j + 2];
        G[ORD-2] = sHi ? 0.f : cG0;
        G[ORD-1] = sHi ? 0.f : cG1;
        x0 = mG[1];                          // new x0 (valid on sub-lane 0)
    }

    // ---- stage 1: each warp reduces its OWN 8 compartment rows ----
    __syncwarp();
    {
        float acc = 0.0f;
        #pragma unroll
        for (int g = 0; g < CPW; ++g) acc += smem[vv][wv * CPW + g][lane];
        part[vv][wv][lane] = acc;
    }
    __syncthreads();

    // ---- stage 2: one warp per voxel sums 5 partials, normalizes by echo 0 ----
    if (wv == 0) {
        float acc = 0.0f;
        #pragma unroll
        for (int ww = 0; ww < WARPS_V; ++ww) acc += part[vv][ww][lane];
        const float acc0 = __shfl_sync(FULL, acc, 0);
        out[b * NE + lane] = __fdividef(acc, acc0);
    }
}

extern "C" void kernel_launch(void* const* d_in, const int* in_sizes, int n_in,
                              void* d_out, int out_size) {
    const float* refoc = (const float*)d_in[0];
    const float* t2s   = (const float*)d_in[1];
    const float* wts   = (const float*)d_in[2];
    float* out = (float*)d_out;
    epg_kernel<<<B_VOX / VPB, THREADS>>>(refoc, t2s, wts, out);
}

// round 13
// speedup vs baseline: 3.7915x; 3.7915x over previous
#include <cuda_runtime.h>

#define B_VOX   256
#define NPC     40
#define NE      32
#define ORD     8                    // EPG orders per lane
#define LPC     4                    // lanes per compartment (32 orders)
#define CPW     8                    // compartments per warp
#define VPB     2                    // voxels per block  (grid=128: measured optimum)
#define WARPS_V (NPC / CPW)          // 5 warps per voxel
#define WARPS   (WARPS_V * VPB)      // 10 warps per block
#define THREADS (WARPS * 32)         // 320

// y-form EPG: y_{k+1} = S^2 · M · y_k  (y = S·x, E = S·M·S, M = D·T·D blockdiag)
// sub-lane s = lane&3 holds orders 8s+1..8s+8 as F[8],G[8],u[8] (u = C·Z);
// compartment = (wz%5)*8 + (lane>>2); voxel = blockIdx.x*VPB + wz/5.
// Weight w folded into initial state (linearity) -> echo_k = mG[0] directly.
// M per order:  mF = A·F + B·G + u ;  mG = B·F + A·G - u
//               u' = CD·(G - F) + Ez·u  (CD = C·Dz) ;  mx0 = e2²·x0
// S² shift: F[0]<-prev mF[6] (s0: mG[0]); F[1]<-prev mF[7] (s0: mx0);
//           F[j]=mF[j-2]; G[j]=mG[j+2]; G[6]<-next mG[0] (s3: 0); G[7]<-next mG[1] (s3: 0)
//           x0<-mG[1] (s0); echo_k = s0 mG[0]

__global__ __launch_bounds__(THREADS) void epg_kernel(
    const float* __restrict__ refoc,    // (256,)
    const float* __restrict__ t2s,      // (256, 40)
    const float* __restrict__ wts,      // (256, 40)
    float* __restrict__ out)            // (256, 32)
{
    const int lane = threadIdx.x & 31;
    const int wz   = threadIdx.x >> 5;
    const int vv   = wz / WARPS_V;           // voxel slot within block
    const int wv   = wz % WARPS_V;           // warp within voxel
    const int b    = blockIdx.x * VPB + vv;
    const int s    = lane & (LPC - 1);
    const int grp  = lane >> 2;
    const bool sLo = (s == 0);
    const bool sHi = (s == LPC - 1);
    const unsigned FULL = 0xFFFFFFFFu;

    __shared__ float smem[VPB][NPC][NE + 1]; // echo rows (+1 pad, conflict-free STS)
    __shared__ float part[VPB][WARPS_V][NE]; // per-warp partials

    // issue all global loads first (overlap latency with MUFU prologue)
    const int   c    = wv * CPW + grp;
    const float t2   = __ldg(&t2s[b * NPC + c]);
    const float w    = __ldg(&wts[b * NPC + c]);
    const float ang  = __ldg(&refoc[b]);

    // per-voxel rotation constants — fast MUFU path
    const float a  = ang * 0.017453292519943295f;
    const float sa = __sinf(a);
    const float ca = __cosf(a);
    const float c2 = 0.5f * (1.0f + ca);     // cos^2(a/2)
    const float s2 = 0.5f * (1.0f - ca);     // sin^2(a/2)
    const float ch = sqrtf(c2);              // a/2 in (60°,90°] -> both roots >= 0
    const float sh = sqrtf(s2);
    const float e1   = 0.99501247919268231f; // exp(-5/1000)
    const float e1sq = e1 * e1;

    // per-compartment fused coefficients — fast exp/rcp
    const float e2   = __expf(-5.0f * __frcp_rn(t2));
    const float e2sq = e2 * e2;
    const float A    = c2 * e2sq;
    const float Bc   = s2 * e2sq;
    const float Cc   = sa * e2 * e1;
    const float Dz   = 0.5f * sa * e1 * e2;
    const float Ez   = ca * e1sq;
    const float CD   = Cc * Dz;              // u-recurrence coefficient

    // init y0 = S·x0, pre-scaled by the compartment weight (linearity)
    float F[ORD], G[ORD], u[ORD];
    #pragma unroll
    for (int j = 0; j < ORD; ++j) { F[j] = 0.f; G[j] = 0.f; u[j] = 0.f; }
    if (sLo) F[0] = w * sh;
    float x0 = w * ch;                       // meaningful on sub-lane 0

    #pragma unroll                            // FULL unroll: no rotation MOVs, no branch
    for (int k = 0; k < NE; ++k) {
        // ---- M = D·T·D (all local, u = C·Z form) ----
        float mF[ORD], mG[ORD];
        #pragma unroll
        for (int j = 0; j < ORD; ++j) {
            mF[j] = fmaf(A,  F[j], fmaf(Bc, G[j],  u[j]));
            mG[j] = fmaf(Bc, F[j], fmaf(A,  G[j], -u[j]));
            u[j]  = fmaf(CD, G[j], fmaf(-CD, F[j], Ez * u[j]));
        }
        const float mx0 = e2sq * x0;

        // ---- S²: one shuffle segment, 4 shfls serve all 8 compartments ----
        const float cF0 = __shfl_up_sync  (FULL, mF[ORD-2], 1, LPC);
        const float cF1 = __shfl_up_sync  (FULL, mF[ORD-1], 1, LPC);
        const float cG0 = __shfl_down_sync(FULL, mG[0],     1, LPC);
        const float cG1 = __shfl_down_sync(FULL, mG[1],     1, LPC);

        if (sLo) smem[vv][c][k] = mG[0];     // pre-weighted echo_k, bare STS

        F[0] = sLo ? mG[0] : cF0;
        F[1] = sLo ? mx0   : cF1;
        #pragma unroll
        for (int j = 2; j < ORD; ++j) F[j] = mF[j - 2];
        #pragma unroll
        for (int j = 0; j < ORD - 2; ++j) G[j] = mG[j + 2];
        G[ORD-2] = sHi ? 0.f : cG0;
        G[ORD-1] = sHi ? 0.f : cG1;
        x0 = mG[1];                          // new x0 (valid on sub-lane 0)
    }

    // ---- stage 1: each warp reduces its OWN 8 compartment rows ----
    __syncwarp();
    {
        float acc = 0.0f;
        #pragma unroll
        for (int g = 0; g < CPW; ++g) acc += smem[vv][wv * CPW + g][lane];
        part[vv][wv][lane] = acc;
    }
    __syncthreads();

    // ---- stage 2: one warp per voxel sums 5 partials, normalizes by echo 0 ----
    if (wv == 0) {
        float acc = 0.0f;
        #pragma unroll
        for (int ww = 0; ww < WARPS_V; ++ww) acc += part[vv][ww][lane];
        const float acc0 = __shfl_sync(FULL, acc, 0);
        out[b * NE + lane] = __fdividef(acc, acc0);
    }
}

extern "C" void kernel_launch(void* const* d_in, const int* in_sizes, int n_in,
                              void* d_out, int out_size) {
    const float* refoc = (const float*)d_in[0];
    const float* t2s   = (const float*)d_in[1];
    const float* wts   = (const float*)d_in[2];
    float* out = (float*)d_out;
    epg_kernel<<<B_VOX / VPB, THREADS>>>(refoc, t2s, wts, out);
}